// round 5
// baseline (speedup 1.0000x reference)
#include <cuda_runtime.h>
#include <math.h>

#define BF    512
#define NTOT  66
#define NOUT  50
#define KK    8
#define T_TOT 2048
#define CT    256      // body steps per fast chunk
#define WUP   128      // warm-up steps (shadowing)
#define DT_F  0.05f

// ---------------- constant tables --------------------------------------------
__device__ double g_D[NTOT * NTOT];
__device__ double g_P[2][NTOT * NTOT];
__device__ float  g_band[17][NOUT];
__device__ float  g_sneg[NTOT];

// staged F for mixed columns: lanes 16..47 -> index lane-16
__device__ float  g_Fm[T_TOT][BF][32];

__global__ void init_kernel() {
    int tid = threadIdx.x;
    const double c = pow(1000.0, 1.0 / 49.0);
    __shared__ double s[NTOT], tau[NTOT];
    if (tid < NTOT) {
        double e = (double)(tid - KK);
        double tv = 0.1 * pow(c, e);
        tau[tid] = tv;
        s[tid] = (double)KK / tv;
        g_sneg[tid] = -(float)s[tid];
    }
    __syncthreads();

    for (int idx = tid; idx < NTOT * NTOT; idx += blockDim.x) g_D[idx] = 0.0;
    __syncthreads();
    if (tid >= 1 && tid <= NTOT - 2) {
        double denom = s[tid + 1] - s[tid - 1];
        g_D[tid * NTOT + tid - 1] = -(1.0 / c) / denom;
        g_D[tid * NTOT + tid]     = (1.0 / c - c) / denom;
        g_D[tid * NTOT + tid + 1] = c / denom;
    }
    __syncthreads();

    for (int idx = tid; idx < NTOT * NTOT; idx += blockDim.x) g_P[1][idx] = g_D[idx];
    __syncthreads();

    for (int k = 2; k <= KK; k++) {
        int src = (k - 1) & 1, dst = k & 1;
        for (int idx = tid; idx < NTOT * NTOT; idx += blockDim.x) {
            int i = idx / NTOT, j = idx % NTOT;
            double acc = g_P[src][i * NTOT + j] * g_D[j * NTOT + j];
            if (j > 0)        acc += g_P[src][i * NTOT + j - 1] * g_D[(j - 1) * NTOT + j];
            if (j < NTOT - 1) acc += g_P[src][i * NTOT + j + 1] * g_D[(j + 1) * NTOT + j];
            g_P[dst][idx] = acc;
        }
        __syncthreads();
    }
    const int fin = KK & 1;

    double lg9 = lgamma(9.0);
    for (int idx = tid; idx < 17 * NOUT; idx += blockDim.x) {
        int d = idx / NOUT, j = idx % NOUT;
        int m = j + KK, n = j + d;
        double w = tau[m] * exp(9.0 * log(s[m]) - lg9);
        g_band[d][j] = (float)(g_P[fin][m * NTOT + n] * w);
    }
}

// one reference-exact logaddexp step
__device__ __forceinline__ float laestep(float carry, float x, float lf, float sneg) {
    float a  = __fadd_rn(carry, __fmul_rn(x, sneg));
    float am = fmaxf(a, lf);
    float dd = __fsub_rn(a, lf);
    return __fadd_rn(am, log1pf(expf(-fabsf(dd))));
}

// 17-tap accumulate over v[9] float2 (lanes jj..jj+16), round-3-proven order
__device__ __forceinline__ void band17(const float2* v, const float* c0, const float* c1,
                                       float& a0, float& a1) {
    a0 = 0.0f; a1 = 0.0f;
#pragma unroll
    for (int i = 0; i < 9; i++) {
        a0 = fmaf(v[i].x, c0[2 * i], a0);
        a1 = fmaf(v[i].y, c1[2 * i], a1);
    }
#pragma unroll
    for (int i = 0; i < 8; i++) {
        a0 = fmaf(v[i].y,     c0[2 * i + 1], a0);
        a1 = fmaf(v[i + 1].x, c1[2 * i + 1], a1);
    }
}

// ---------------- main kernel: SLOW blocks + FAST chunk blocks ---------------
__global__ void __launch_bounds__(128) main_kernel(
    const float* __restrict__ f, const float* __restrict__ alpha,
    const float* __restrict__ delta,
    float* __restrict__ til, float* __restrict__ hout, float* __restrict__ Fout) {
    __shared__ float2 shXL[2][32];
    __shared__ float  shF[2][32][36];

    const int bid = blockIdx.x;
    const int tid = threadIdx.x;

    if (bid < BF) {
        // ================= SLOW role: lanes 32..65, full-T sequential =======
        const int cb = bid;
        float sneg = 0.f, sneg2 = 0.f, carry = -INFINITY, carry2 = -INFINITY;
        if (tid < 32) { sneg = g_sneg[32 + tid]; if (tid < 2) sneg2 = g_sneg[64 + tid]; }

        int p = 0, q = 0; bool mv = false;
        float c0[17], c1[17];
        if (tid >= 64 && tid - 64 < 63) {
            mv = true; p = (tid - 64) % 9; q = (tid - 64) / 9;
#pragma unroll
            for (int d = 0; d < 17; d++) {
                c0[d] = g_band[d][32 + 2 * p];
                c1[d] = g_band[d][33 + 2 * p];
            }
        }

        if (tid >= 32 && tid < 64) {     // prologue: tile 0 inputs
            int lt = tid - 32;
            size_t idx = (size_t)lt * BF + cb;
            float fv = __ldg(&f[idx]), av = __ldg(&alpha[idx]), dv = __ldg(&delta[idx]);
            shXL[0][lt] = make_float2(__fadd_rn(__fmul_rn(av, DT_F), dv),
                                      logf(__fmul_rn(fv, DT_F)));
        }
        __syncthreads();

        for (int k = 0; k < 64; k++) {
            const int cur = k & 1, prv = cur ^ 1;
            if (tid < 32) {
#pragma unroll 8
                for (int j = 0; j < 32; j++) {
                    float2 v = shXL[cur][j];
                    carry = laestep(carry, v.x, v.y, sneg);
                    shF[cur][j][tid] = __expf(carry);
                    if (tid < 2) {
                        carry2 = laestep(carry2, v.x, v.y, sneg2);
                        shF[cur][j][32 + tid] = __expf(carry2);
                    }
                }
            } else if (tid < 64) {
                if (k + 1 < 64) {
                    int lt = tid - 32;
                    size_t idx = (size_t)((k + 1) * 32 + lt) * BF + cb;
                    float fv = __ldg(&f[idx]), av = __ldg(&alpha[idx]), dv = __ldg(&delta[idx]);
                    shXL[prv][lt] = make_float2(__fadd_rn(__fmul_rn(av, DT_F), dv),
                                                logf(__fmul_rn(fv, DT_F)));
                }
            } else if (mv && k > 0) {
                const int t0 = (k - 1) * 32;
                for (int tl = q; tl < 32; tl += 7) {
                    const float* Fr = shF[prv][tl];
                    float2 v[9];
#pragma unroll
                    for (int i = 0; i < 9; i++) v[i] = *(const float2*)(Fr + 2 * p + 2 * i);
                    float a0, a1; band17(v, c0, c1, a0, a1);
                    size_t rb = ((size_t)(t0 + tl) * BF + cb) * NOUT;
                    __stcs((float2*)(til  + rb + 32 + 2 * p), make_float2(a0, a1));
                    __stcs((float2*)(Fout + rb + 24 + 2 * p), v[0]);      // lanes 32+2p,33+2p
                    if (p < 4) {
                        float2 w = *(const float2*)(Fr + 18 + 2 * p);     // lanes 50+2p,51+2p
                        __stcs((float2*)(Fout + rb + 42 + 2 * p), w);
                    }
                    if (p < 8)
                        __stcs((float2*)(&g_Fm[t0 + tl][cb][16 + 2 * p]), v[0]);
                }
            }
            __syncthreads();
        }
        // epilogue: last tile + h
        if (tid < 32) {
            hout[(size_t)cb * NTOT + 32 + tid] = carry;
            if (tid < 2) hout[(size_t)cb * NTOT + 64 + tid] = carry2;
        } else if (mv) {
            const int t0 = 63 * 32;
            for (int tl = q; tl < 32; tl += 7) {
                const float* Fr = shF[1][tl];
                float2 v[9];
#pragma unroll
                for (int i = 0; i < 9; i++) v[i] = *(const float2*)(Fr + 2 * p + 2 * i);
                float a0, a1; band17(v, c0, c1, a0, a1);
                size_t rb = ((size_t)(t0 + tl) * BF + cb) * NOUT;
                __stcs((float2*)(til  + rb + 32 + 2 * p), make_float2(a0, a1));
                __stcs((float2*)(Fout + rb + 24 + 2 * p), v[0]);
                if (p < 4) {
                    float2 w = *(const float2*)(Fr + 18 + 2 * p);
                    __stcs((float2*)(Fout + rb + 42 + 2 * p), w);
                }
                if (p < 8)
                    __stcs((float2*)(&g_Fm[t0 + tl][cb][16 + 2 * p]), v[0]);
            }
        }
    } else {
        // ================= FAST role: lanes 0..31, chunk + warm-up ==========
        const int e  = bid - BF;
        const int c  = e >> 9;          // chunk 0..7
        const int cb = e & 511;
        const int tbeg      = c * CT - (c ? WUP : 0);
        const int ntile     = c ? (CT + WUP) / 32 : CT / 32;   // 12 or 8
        const int bodyStart = c ? WUP / 32 : 0;                // 4 or 0

        float sneg = 0.f, carry = -INFINITY;
        if (tid < 32) sneg = g_sneg[tid];

        int p = 0, q = 0; bool mv = (tid >= 64);
        float c0[17], c1[17];
        if (mv) {
            p = (tid - 64) & 7; q = (tid - 64) >> 3;
#pragma unroll
            for (int d = 0; d < 17; d++) {
                c0[d] = g_band[d][2 * p];
                c1[d] = g_band[d][2 * p + 1];
            }
        }

        if (tid >= 32 && tid < 64) {
            int lt = tid - 32;
            size_t idx = (size_t)(tbeg + lt) * BF + cb;
            float fv = __ldg(&f[idx]), av = __ldg(&alpha[idx]), dv = __ldg(&delta[idx]);
            shXL[0][lt] = make_float2(__fadd_rn(__fmul_rn(av, DT_F), dv),
                                      logf(__fmul_rn(fv, DT_F)));
        }
        __syncthreads();

        for (int k = 0; k < ntile; k++) {
            const int cur = k & 1, prv = cur ^ 1;
            if (tid < 32) {
#pragma unroll 8
                for (int j = 0; j < 32; j++) {
                    float2 v = shXL[cur][j];
                    carry = laestep(carry, v.x, v.y, sneg);
                    shF[cur][j][tid] = __expf(carry);
                }
            } else if (tid < 64) {
                if (k + 1 < ntile) {
                    int lt = tid - 32;
                    size_t idx = (size_t)(tbeg + (k + 1) * 32 + lt) * BF + cb;
                    float fv = __ldg(&f[idx]), av = __ldg(&alpha[idx]), dv = __ldg(&delta[idx]);
                    shXL[prv][lt] = make_float2(__fadd_rn(__fmul_rn(av, DT_F), dv),
                                                logf(__fmul_rn(fv, DT_F)));
                }
            } else if (k > bodyStart) {
                const int t0 = tbeg + (k - 1) * 32;
                for (int tl = q; tl < 32; tl += 8) {
                    const float* Fr = shF[prv][tl];
                    float2 v[9];
#pragma unroll
                    for (int i = 0; i < 9; i++) v[i] = *(const float2*)(Fr + 2 * p + 2 * i);
                    float a0, a1; band17(v, c0, c1, a0, a1);
                    size_t rb = ((size_t)(t0 + tl) * BF + cb) * NOUT;
                    __stcs((float2*)(til  + rb + 2 * p), make_float2(a0, a1));
                    __stcs((float2*)(Fout + rb + 2 * p), v[4]);           // lanes 2p+8,2p+9
                    if (p < 4) {
                        float2 w = *(const float2*)(Fr + 24 + 2 * p);     // lanes 24+2p..
                        __stcs((float2*)(Fout + rb + 16 + 2 * p), w);
                    }
                    float2 u = *(const float2*)(Fr + 16 + 2 * p);         // lanes 16+2p..
                    __stcs((float2*)(&g_Fm[t0 + tl][cb][2 * p]), u);
                }
            }
            __syncthreads();
        }
        // epilogue: last tile + h (chunk 7)
        if (tid < 32) {
            if (c == 7) hout[(size_t)cb * NTOT + tid] = carry;
        } else if (mv) {
            const int t0 = tbeg + (ntile - 1) * 32;
            const int buf = (ntile - 1) & 1;
            for (int tl = q; tl < 32; tl += 8) {
                const float* Fr = shF[buf][tl];
                float2 v[9];
#pragma unroll
                for (int i = 0; i < 9; i++) v[i] = *(const float2*)(Fr + 2 * p + 2 * i);
                float a0, a1; band17(v, c0, c1, a0, a1);
                size_t rb = ((size_t)(t0 + tl) * BF + cb) * NOUT;
                __stcs((float2*)(til  + rb + 2 * p), make_float2(a0, a1));
                __stcs((float2*)(Fout + rb + 2 * p), v[4]);
                if (p < 4) {
                    float2 w = *(const float2*)(Fr + 24 + 2 * p);
                    __stcs((float2*)(Fout + rb + 16 + 2 * p), w);
                }
                float2 u = *(const float2*)(Fr + 16 + 2 * p);
                __stcs((float2*)(&g_Fm[t0 + tl][cb][2 * p]), u);
            }
        }
    }
}

// ---------------- mixed-column kernel: til cols 16..31 -----------------------
__global__ void __launch_bounds__(128) mv_kernel(float* __restrict__ til) {
    __shared__ float sF[64][36];
    const int tt = blockIdx.x, cb = blockIdx.y;
    const int t0 = tt * 64, tid = threadIdx.x;

    for (int l = tid; l < 512; l += 128) {
        int row = l >> 3, c4 = l & 7;
        float4 v = *(const float4*)(&g_Fm[t0 + row][cb][c4 * 4]);
        *(float4*)(&sF[row][c4 * 4]) = v;
    }
    const int p = tid >> 4, tg = tid & 15;
    float c0[17], c1[17];
#pragma unroll
    for (int d = 0; d < 17; d++) {
        c0[d] = g_band[d][16 + 2 * p];
        c1[d] = g_band[d][17 + 2 * p];
    }
    __syncthreads();

#pragma unroll
    for (int it = 0; it < 4; it++) {
        int t = tg + 16 * it;
        const float* Fr = sF[t];
        float2 v[9];
#pragma unroll
        for (int i = 0; i < 9; i++) v[i] = *(const float2*)(Fr + 2 * p + 2 * i);
        float a0, a1; band17(v, c0, c1, a0, a1);
        size_t rb = ((size_t)(t0 + t) * BF + cb) * NOUT;
        __stcs((float2*)(til + rb + 16 + 2 * p), make_float2(a0, a1));
    }
}

// ---------------- launch ------------------------------------------------------
extern "C" void kernel_launch(void* const* d_in, const int* in_sizes, int n_in,
                              void* d_out, int out_size) {
    const float* f     = (const float*)d_in[0];
    const float* alpha = (const float*)d_in[1];
    const float* delta = (const float*)d_in[2];

    float* out  = (float*)d_out;
    size_t tsz  = (size_t)T_TOT * BF * NOUT;
    float* til  = out;
    float* hptr = out + tsz;
    float* Fo   = out + tsz + (size_t)BF * NTOT;

    init_kernel<<<1, 1024>>>();
    main_kernel<<<BF + 8 * BF, 128>>>(f, alpha, delta, til, hptr, Fo);
    mv_kernel<<<dim3(T_TOT / 64, BF), 128>>>(til);
}

// round 6
// speedup vs baseline: 1.9288x; 1.9288x over previous
#include <cuda_runtime.h>
#include <math.h>

#define BF     512
#define NTOT   66
#define NOUT   50
#define KK     8
#define T_TOT  2048
#define TILE   32
#define NTILE  (T_TOT / TILE)
#define DT_F   0.05f
#define FPAD   68

// ---------------- constant tables -------------------------------------------
__device__ float g_band[17][NOUT];   // g_band[d][j] = POST[j+d][j+8]
__device__ float g_sneg[NTOT];       // -(float)s_full[n]

// ---------------- fast init: one block per output column --------------------
// Computes row (j+8) of D^8 via 8 banded row-times-matrix products in shared
// fp64, with the SAME per-entry op order as the previous (validated) init.
__global__ void init_kernel() {
    __shared__ double s[NTOT], dl[NTOT], dm[NTOT], du[NTOT];
    __shared__ double r[2][NTOT];
    const int j   = blockIdx.x;      // 0..49
    const int tid = threadIdx.x;     // 0..95
    const double c = pow(1000.0, 1.0 / 49.0);

    if (tid < NTOT) {
        double tv = 0.1 * pow(c, (double)(tid - KK));
        s[tid] = (double)KK / tv;
        if (j == 0) g_sneg[tid] = -(float)s[tid];
    }
    __syncthreads();
    if (tid < NTOT) {
        if (tid >= 1 && tid <= NTOT - 2) {
            double denom = s[tid + 1] - s[tid - 1];
            dl[tid] = -(1.0 / c) / denom;        // D[i][i-1]
            dm[tid] = (1.0 / c - c) / denom;     // D[i][i]
            du[tid] = c / denom;                 // D[i][i+1]
        } else {
            dl[tid] = dm[tid] = du[tid] = 0.0;
        }
        r[0][tid] = (tid == j + KK) ? 1.0 : 0.0;
    }
    __syncthreads();

    for (int k = 1; k <= KK; k++) {
        int src = (k - 1) & 1, dst = k & 1;
        if (tid < NTOT) {
            // identical term order to the old validated init: mid, left, right
            double acc = r[src][tid] * dm[tid];
            if (tid > 0)        acc += r[src][tid - 1] * du[tid - 1];
            if (tid < NTOT - 1) acc += r[src][tid + 1] * dl[tid + 1];
            r[dst][tid] = acc;
        }
        __syncthreads();
    }
    // D^8 row (j+8) now in r[0]
    if (tid < 17) {
        int m = j + KK;
        double tau = 0.1 * pow(c, (double)(m - KK));
        double w = tau * exp(9.0 * log(s[m]) - lgamma(9.0));
        g_band[tid][j] = (float)(r[0][j + tid] * w);
    }
}

// ---------------- bit-exact logaddexp step ----------------------------------
__device__ __forceinline__ float laestep(float carry, float x, float lf, float sneg) {
    float a  = __fadd_rn(carry, __fmul_rn(x, sneg));
    float am = fmaxf(a, lf);
    float dd = __fsub_rn(a, lf);
    return __fadd_rn(am, log1pf(expf(-fabsf(dd))));
}

// ---------------- packed f32x2 helpers ---------------------------------------
__device__ __forceinline__ unsigned long long pack2(float lo, float hi) {
    unsigned long long u;
    asm("mov.b64 %0, {%1, %2};" : "=l"(u) : "f"(lo), "f"(hi));
    return u;
}
__device__ __forceinline__ unsigned long long fma2(unsigned long long a,
                                                   unsigned long long b,
                                                   unsigned long long c) {
    unsigned long long d;
    asm("fma.rn.f32x2 %0, %1, %2, %3;" : "=l"(d) : "l"(a), "l"(b), "l"(c));
    return d;
}

// ---------------- fused scan + banded einsum, 2 chains per block -------------
__global__ void __launch_bounds__(288) main_kernel(
    const float* __restrict__ f, const float* __restrict__ alpha,
    const float* __restrict__ delta,
    float* __restrict__ til, float* __restrict__ hout, float* __restrict__ Fout) {
    __shared__ float2 shXL[2][2][TILE];          // [buf][chain][row]
    __shared__ float  shF[2][2][TILE][FPAD];     // [buf][chain][row][lane]

    const int b   = blockIdx.x;
    const int cbA = 2 * b;                       // chains cbA, cbA+1
    const int tid = threadIdx.x;

    // ---- roles ----
    const bool scanMain = (tid < 128);           // warps 0-3: lanes 0-63 x 2 chains
    const int  sChain   = (tid >> 6) & 1;
    const int  sLane    = tid & 63;

    const bool w4      = (tid >= 128 && tid < 160);
    const int  e       = tid - 128;
    const bool xScan   = w4 && (e < 4);          // lanes 64,65 x 2 chains
    const int  xChain  = e >> 1;
    const int  xLane   = 64 + (e & 1);
    const bool isLoad  = w4 && (e >= 4);
    const int  lt      = e - 4;                  // 0..27

    const int  mt      = tid - 160;              // matvec: warps 5-8
    const bool mvAct   = (tid >= 160) && (mt < 100);
    const int  combo   = mvAct ? (mt % 50) : 0;
    const int  tq      = mvAct ? (mt / 50) : 0;  // row parity
    const int  mChain  = combo / 25;
    const int  jj      = 2 * (combo % 25);

    float sneg = 0.0f, carry = -INFINITY;
    if (scanMain)   sneg = g_sneg[sLane];
    else if (xScan) sneg = g_sneg[xLane];

    unsigned long long C[17];
    if (mvAct) {
#pragma unroll
        for (int d = 0; d < 17; d++)
            C[d] = pack2(g_band[d][jj], g_band[d][jj + 1]);
    }

    // ---- prologue: loader fills tile 0 ----
    if (isLoad) {
#pragma unroll
        for (int rr = 0; rr < 2; rr++) {
            int row = lt + rr * 28;
            if (row < TILE) {
                size_t g = (size_t)row * BF + cbA;
                float2 fv = __ldg((const float2*)(f + g));
                float2 av = __ldg((const float2*)(alpha + g));
                float2 dv = __ldg((const float2*)(delta + g));
                shXL[0][0][row] = make_float2(__fadd_rn(__fmul_rn(av.x, DT_F), dv.x),
                                              logf(__fmul_rn(fv.x, DT_F)));
                shXL[0][1][row] = make_float2(__fadd_rn(__fmul_rn(av.y, DT_F), dv.y),
                                              logf(__fmul_rn(fv.y, DT_F)));
            }
        }
    }
    __syncthreads();

    for (int k = 0; k < NTILE; k++) {
        const int cur = k & 1, prv = cur ^ 1;
        if (scanMain) {
#pragma unroll 8
            for (int j = 0; j < TILE; j++) {
                float2 v = shXL[cur][sChain][j];
                carry = laestep(carry, v.x, v.y, sneg);
                shF[cur][sChain][j][sLane] = __expf(carry);
            }
        } else if (w4) {
            if (xScan) {
#pragma unroll 8
                for (int j = 0; j < TILE; j++) {
                    float2 v = shXL[cur][xChain][j];
                    carry = laestep(carry, v.x, v.y, sneg);
                    shF[cur][xChain][j][xLane] = __expf(carry);
                }
            } else if (k + 1 < NTILE) {
                const int tn = (k + 1) * TILE;
#pragma unroll
                for (int rr = 0; rr < 2; rr++) {
                    int row = lt + rr * 28;
                    if (row < TILE) {
                        size_t g = (size_t)(tn + row) * BF + cbA;
                        float2 fv = __ldg((const float2*)(f + g));
                        float2 av = __ldg((const float2*)(alpha + g));
                        float2 dv = __ldg((const float2*)(delta + g));
                        shXL[prv][0][row] = make_float2(__fadd_rn(__fmul_rn(av.x, DT_F), dv.x),
                                                        logf(__fmul_rn(fv.x, DT_F)));
                        shXL[prv][1][row] = make_float2(__fadd_rn(__fmul_rn(av.y, DT_F), dv.y),
                                                        logf(__fmul_rn(fv.y, DT_F)));
                    }
                }
            }
        } else if (mvAct && k > 0) {
            const int t0 = (k - 1) * TILE;
            const int cb = cbA + mChain;
            for (int row = tq; row < TILE; row += 2) {
                const float* Fr = shF[prv][mChain][row];
                float2 v[9];
#pragma unroll
                for (int i = 0; i < 9; i++) v[i] = *(const float2*)(Fr + jj + 2 * i);
                unsigned long long acc = 0ULL;   // (0.f, 0.f)
#pragma unroll
                for (int i = 0; i < 17; i++) {
                    unsigned long long p = (i & 1)
                        ? pack2(v[i >> 1].y, v[(i >> 1) + 1].x)
                        : pack2(v[i >> 1].x, v[i >> 1].y);
                    acc = fma2(p, C[i], acc);
                }
                float a0, a1;
                asm("mov.b64 {%0, %1}, %2;" : "=f"(a0), "=f"(a1) : "l"(acc));
                size_t rb = ((size_t)(t0 + row) * BF + cb) * NOUT + jj;
                __stcs((float2*)(til  + rb), make_float2(a0, a1));
                __stcs((float2*)(Fout + rb), v[4]);   // F[jj+8], F[jj+9]
            }
        }
        __syncthreads();
    }

    // ---- epilogue ----
    if (scanMain) {
        hout[(size_t)(cbA + sChain) * NTOT + sLane] = carry;
    } else if (xScan) {
        hout[(size_t)(cbA + xChain) * NTOT + xLane] = carry;
    } else if (mvAct) {
        const int t0 = (NTILE - 1) * TILE;
        const int prv = (NTILE - 1) & 1;
        const int cb = cbA + mChain;
        for (int row = tq; row < TILE; row += 2) {
            const float* Fr = shF[prv][mChain][row];
            float2 v[9];
#pragma unroll
            for (int i = 0; i < 9; i++) v[i] = *(const float2*)(Fr + jj + 2 * i);
            unsigned long long acc = 0ULL;
#pragma unroll
            for (int i = 0; i < 17; i++) {
                unsigned long long p = (i & 1)
                    ? pack2(v[i >> 1].y, v[(i >> 1) + 1].x)
                    : pack2(v[i >> 1].x, v[i >> 1].y);
                acc = fma2(p, C[i], acc);
            }
            float a0, a1;
            asm("mov.b64 {%0, %1}, %2;" : "=f"(a0), "=f"(a1) : "l"(acc));
            size_t rb = ((size_t)(t0 + row) * BF + cb) * NOUT + jj;
            __stcs((float2*)(til  + rb), make_float2(a0, a1));
            __stcs((float2*)(Fout + rb), v[4]);
        }
    }
}

// ---------------- launch ------------------------------------------------------
extern "C" void kernel_launch(void* const* d_in, const int* in_sizes, int n_in,
                              void* d_out, int out_size) {
    const float* f     = (const float*)d_in[0];
    const float* alpha = (const float*)d_in[1];
    const float* delta = (const float*)d_in[2];

    float* out  = (float*)d_out;
    size_t tsz  = (size_t)T_TOT * BF * NOUT;
    float* til  = out;
    float* hptr = out + tsz;
    float* Fo   = out + tsz + (size_t)BF * NTOT;

    init_kernel<<<NOUT, 96>>>();
    main_kernel<<<BF / 2, 288>>>(f, alpha, delta, til, hptr, Fo);
}